// round 13
// baseline (speedup 1.0000x reference)
#include <cuda_runtime.h>
#include <cuda_bf16.h>
#include <math.h>

// Problem constants
#define T_TOK 2048   // B*S
#define E_DIM 512
#define N_SEC 8
#define M_MEM 2048
#define KD 32
#define VD 32
#define TOPK 4
#define CAND 8       // approximate candidates kept per (token, sector)

// Scratch (device globals; no runtime allocation allowed)
__device__ float g_xemb[T_TOK * E_DIM];      // 4 MB
__device__ float g_q[T_TOK * KD];
__device__ float g_sdist[T_TOK * N_SEC];
__device__ int   g_top8i[T_TOK * N_SEC * CAND];

// ---------------------------------------------------------------------------
// Kernel 1: embedding gather + sector softmax + token query (1 block / token)
// ---------------------------------------------------------------------------
__global__ void k_embed(const int* __restrict__ x, const float* __restrict__ emb,
                        const float* __restrict__ skeys, const float* __restrict__ Wq,
                        const float* __restrict__ bq, float* __restrict__ out_sdist)
{
    const int t = blockIdx.x;
    const int tid = threadIdx.x;          // 128 threads
    __shared__ __align__(16) float xs[E_DIM];
    __shared__ float red[128];
    __shared__ float ssc[N_SEC];

    const int xi = x[t];
    float4 v = ((const float4*)(emb + (size_t)xi * E_DIM))[tid];
    ((float4*)xs)[tid] = v;
    ((float4*)(g_xemb + (size_t)t * E_DIM))[tid] = v;

    #pragma unroll
    for (int n = 0; n < N_SEC; n++) {
        const float* sk = skeys + n * E_DIM + tid * 4;
        float p = v.x * sk[0] + v.y * sk[1] + v.z * sk[2] + v.w * sk[3];
        #pragma unroll
        for (int o = 16; o > 0; o >>= 1) p += __shfl_down_sync(0xffffffffu, p, o);
        if ((tid & 31) == 0) red[n * 4 + (tid >> 5)] = p;
    }
    __syncthreads();
    if (tid < N_SEC)
        ssc[tid] = red[tid*4] + red[tid*4+1] + red[tid*4+2] + red[tid*4+3];
    __syncthreads();
    if (tid == 0) {
        float mx = ssc[0];
        #pragma unroll
        for (int i = 1; i < N_SEC; i++) mx = fmaxf(mx, ssc[i]);
        float ex[N_SEC]; float sum = 0.f;
        #pragma unroll
        for (int i = 0; i < N_SEC; i++) { ex[i] = expf(ssc[i] - mx); sum += ex[i]; }
        float inv = 1.f / sum;
        #pragma unroll
        for (int i = 0; i < N_SEC; i++) {
            float d = ex[i] * inv;
            out_sdist[t * N_SEC + i] = d;
            g_sdist[t * N_SEC + i]   = d;
        }
    }
    // token query q = xs @ Wq + bq  (Wq is [E, KD] row-major)
    {
        const int kd = tid & 31;
        const int ch = tid >> 5;
        const int e0 = ch * 128;
        float p = 0.f;
        #pragma unroll 8
        for (int e = 0; e < 128; e++)
            p += xs[e0 + e] * Wq[(e0 + e) * KD + kd];
        __syncthreads();
        red[tid] = p;
        __syncthreads();
        if (tid < KD)
            g_q[t * KD + tid] = red[tid] + red[tid + 32] + red[tid + 64] + red[tid + 96] + bq[tid];
    }
}

// ---------------------------------------------------------------------------
// Kernel 2: TF32 tensor-core score GEMM + running approx top-8 per (t, n)
// Grid (T_TOK/BM, N_SEC), 256 thr. Block 128(M)x128(N), warps 2(M)x4(N),
// warp tile 64x32. 3-stage cp.async pipeline, 1 __syncthreads per k-stage.
// ---------------------------------------------------------------------------
#define BM 128
#define BN 128
#define BK 32
#define LDA 36     // As row stride (floats)
#define LDB 36     // Bs row stride (floats)
#define LDSC 132   // Sc row stride (floats)
#define NKT (E_DIM / BK)   // 16 k-stages
#define STG_A (BM * LDA)   // 4608 floats per A stage
#define STG_B (BN * LDB)   // 4608 floats per B stage
#define K2_SMEM_BYTES ((3 * STG_A + 3 * STG_B) * 4)   // 110592

__device__ __forceinline__ void cp16(unsigned dst_smem, const void* src) {
    asm volatile("cp.async.cg.shared.global [%0], [%1], 16;"
                 :: "r"(dst_smem), "l"(src));
}

__global__ void __launch_bounds__(256, 1)
k_scores_topk(const float* __restrict__ mkeys)
{
    const int n  = blockIdx.y;
    const int t0 = blockIdx.x * BM;
    const int tid  = threadIdx.x;
    const int lane = tid & 31, warp = tid >> 5;
    const int wm = (warp & 1) * 64;       // warp M offset (warp tile 64x32)
    const int wn = (warp >> 1) * 32;      // warp N offset
    const int g  = lane >> 2, t4 = lane & 3;

    extern __shared__ __align__(16) unsigned sh[];
    unsigned* AsBase = sh;                       // 3 stages of [BM][LDA]
    unsigned* BsBase = sh + 3 * STG_A;           // 3 stages of [BN][LDB]
    float*    Sc     = (float*)sh;               // aliases stages (needs 67584 B)

    const unsigned sAs = (unsigned)__cvta_generic_to_shared(AsBase);
    const unsigned sBs = (unsigned)__cvta_generic_to_shared(BsBase);

    const float* Bg = mkeys + (size_t)n * M_MEM * E_DIM;
    const float* Ag = g_xemb + (size_t)t0 * E_DIM;

    // running approx top-8 (valid for tid < BM; token = t0 + tid)
    float rv[CAND]; int ri[CAND];
    #pragma unroll
    for (int i = 0; i < CAND; i++) { rv[i] = -1e30f; ri[i] = 0; }

    for (int m0 = 0; m0 < M_MEM; m0 += BN) {
        float acc[4][4][4];
        #pragma unroll
        for (int mi = 0; mi < 4; mi++)
            #pragma unroll
            for (int ni = 0; ni < 4; ni++)
                #pragma unroll
                for (int c = 0; c < 4; c++) acc[mi][ni][c] = 0.f;

        // ---- issue stage 0 ----  (1024 x 16B per tile: 4 per thread each)
        {
            #pragma unroll
            for (int l = 0; l < 4; l++) {
                int lin = tid + l * 256;
                cp16(sAs + (0 * STG_A + (lin >> 3) * LDA + ((lin & 7) << 2)) * 4,
                     Ag + (size_t)(lin >> 3) * E_DIM + ((lin & 7) << 2));
            }
            #pragma unroll
            for (int l = 0; l < 4; l++) {
                int lin = tid + l * 256;
                cp16(sBs + (0 * STG_B + (lin >> 3) * LDB + ((lin & 7) << 2)) * 4,
                     Bg + (size_t)(m0 + (lin >> 3)) * E_DIM + ((lin & 7) << 2));
            }
            asm volatile("cp.async.commit_group;" ::: "memory");
        }

        for (int kt = 0; kt < NKT; kt++) {
            const int cur = kt % 3;
            if (kt < NKT - 1) {
                const int nxt = (kt + 1) % 3;
                const int k0 = (kt + 1) * BK;
                #pragma unroll
                for (int l = 0; l < 4; l++) {
                    int lin = tid + l * 256;
                    cp16(sAs + (nxt * STG_A + (lin >> 3) * LDA + ((lin & 7) << 2)) * 4,
                         Ag + (size_t)(lin >> 3) * E_DIM + k0 + ((lin & 7) << 2));
                }
                #pragma unroll
                for (int l = 0; l < 4; l++) {
                    int lin = tid + l * 256;
                    cp16(sBs + (nxt * STG_B + (lin >> 3) * LDB + ((lin & 7) << 2)) * 4,
                         Bg + (size_t)(m0 + (lin >> 3)) * E_DIM + k0 + ((lin & 7) << 2));
                }
                asm volatile("cp.async.commit_group;" ::: "memory");
                asm volatile("cp.async.wait_group 1;" ::: "memory");   // stage kt arrived
            } else {
                asm volatile("cp.async.wait_group 0;" ::: "memory");   // drain all
            }
            __syncthreads();   // stage kt visible to all; mma(kt-1) of all warps done

            const unsigned* As = AsBase + cur * STG_A;
            const unsigned* Bs = BsBase + cur * STG_B;
            #pragma unroll
            for (int ks = 0; ks < 4; ks++) {
                const int kb = ks * 8;
                unsigned a[4][4], b[4][2];
                #pragma unroll
                for (int mi = 0; mi < 4; mi++) {
                    int tr = wm + mi * 16 + g;
                    a[mi][0] = As[ tr      * LDA + kb + t4    ];
                    a[mi][1] = As[(tr + 8) * LDA + kb + t4    ];
                    a[mi][2] = As[ tr      * LDA + kb + t4 + 4];
                    a[mi][3] = As[(tr + 8) * LDA + kb + t4 + 4];
                }
                #pragma unroll
                for (int ni = 0; ni < 4; ni++) {
                    int cc = wn + ni * 8 + g;
                    b[ni][0] = Bs[cc * LDB + kb + t4    ];
                    b[ni][1] = Bs[cc * LDB + kb + t4 + 4];
                }
                #pragma unroll
                for (int mi = 0; mi < 4; mi++)
                    #pragma unroll
                    for (int ni = 0; ni < 4; ni++) {
                        asm volatile(
                            "mma.sync.aligned.m16n8k8.row.col.f32.tf32.tf32.f32 "
                            "{%0,%1,%2,%3}, {%4,%5,%6,%7}, {%8,%9}, {%0,%1,%2,%3};\n"
                            : "+f"(acc[mi][ni][0]), "+f"(acc[mi][ni][1]),
                              "+f"(acc[mi][ni][2]), "+f"(acc[mi][ni][3])
                            : "r"(a[mi][0]), "r"(a[mi][1]), "r"(a[mi][2]), "r"(a[mi][3]),
                              "r"(b[ni][0]), "r"(b[ni][1]));
                    }
            }
        }
        __syncthreads();   // all warps done with mma reads (Sc aliases stages)

        // write score tile from C fragments
        #pragma unroll
        for (int mi = 0; mi < 4; mi++) {
            #pragma unroll
            for (int ni = 0; ni < 4; ni++) {
                int row = wm + mi * 16 + g;
                int col = wn + ni * 8 + 2 * t4;
                *(float2*)(Sc + row * LDSC + col) =
                    make_float2(acc[mi][ni][0], acc[mi][ni][1]);
                *(float2*)(Sc + (row + 8) * LDSC + col) =
                    make_float2(acc[mi][ni][2], acc[mi][ni][3]);
            }
        }
        __syncthreads();
        if (tid < BM) {
            const float4* rowp = (const float4*)(Sc + tid * LDSC);
            #pragma unroll 4
            for (int q = 0; q < BN / 4; q++) {
                float4 s4 = rowp[q];
                const float sv[4] = {s4.x, s4.y, s4.z, s4.w};
                #pragma unroll
                for (int e = 0; e < 4; e++) {
                    float s = sv[e];
                    if (s > rv[CAND-1]) {
                        float cs = s; int ci = m0 + q * 4 + e;
                        #pragma unroll
                        for (int p = 0; p < CAND; p++) {
                            if (cs > rv[p]) {
                                float tv = rv[p]; int ti = ri[p];
                                rv[p] = cs; ri[p] = ci; cs = tv; ci = ti;
                            }
                        }
                    }
                }
            }
        }
        __syncthreads();   // scan done before next m-tile's cp.async overwrites stages
    }

    if (tid < BM) {
        size_t base = ((size_t)(t0 + tid) * N_SEC + n) * CAND;
        #pragma unroll
        for (int j = 0; j < CAND; j++) g_top8i[base + j] = ri[j];
    }
}

// ---------------------------------------------------------------------------
// Kernel 3 (fused tail): exact fp32 rescore of the 8 candidates -> top-4
// weights (in smem), then ctx gather + sector mix + proj + residual + LN.
// 1 block / token, 256 threads; rescore warp n = sector n.
// ---------------------------------------------------------------------------
__global__ void k_tail(const float* __restrict__ mkeys,
                       const float* __restrict__ knowledge,
                       const float* __restrict__ Wo, const float* __restrict__ bo,
                       const float* __restrict__ gamma, const float* __restrict__ beta,
                       float* __restrict__ out)
{
    const int t = blockIdx.x;
    const int tid = threadIdx.x;          // 256 threads
    const int lane = tid & 31, warp = tid >> 5;
    __shared__ __align__(16) float xs[E_DIM];
    __shared__ float sc8[N_SEC][CAND];
    __shared__ float topw_s[N_SEC][TOPK];
    __shared__ int   topi_s[N_SEC][TOPK];
    __shared__ float qs[KD], sd[N_SEC], fin[VD];
    __shared__ float part[8 * 32];
    __shared__ float red[16];
    __shared__ float s_mu, s_inv;

    if (tid < 128)
        ((float4*)xs)[tid] = ((const float4*)(g_xemb + (size_t)t * E_DIM))[tid];
    if (tid < KD)    qs[tid] = g_q[t * KD + tid];
    if (tid < N_SEC) sd[tid] = g_sdist[t * N_SEC + tid];
    __syncthreads();

    // ---- phase 1: exact rescore (warp = sector) ----
    const int n = warp;
    const size_t cbase = ((size_t)t * N_SEC + n) * CAND;
    const float4* xp = (const float4*)(xs + lane * 16);
    #pragma unroll
    for (int j = 0; j < CAND; j++) {
        const int mi = g_top8i[cbase + j];
        const float4* mk = (const float4*)(mkeys + ((size_t)n * M_MEM + mi) * E_DIM + lane * 16);
        float p = 0.f;
        #pragma unroll
        for (int q = 0; q < 4; q++) {
            float4 a = xp[q], b = mk[q];
            p += a.x*b.x + a.y*b.y + a.z*b.z + a.w*b.w;
        }
        #pragma unroll
        for (int o = 16; o > 0; o >>= 1) p += __shfl_down_sync(0xffffffffu, p, o);
        if (lane == 0) sc8[n][j] = p;
    }
    if (lane == 0) {
        float sv[CAND]; int si[CAND];
        #pragma unroll
        for (int i = 0; i < CAND; i++) { sv[i] = -1e30f; si[i] = 0x7fffffff; }
        #pragma unroll
        for (int j = 0; j < CAND; j++) {
            float cs = sc8[n][j]; int ci = g_top8i[cbase + j];
            #pragma unroll
            for (int p = 0; p < CAND; p++) {
                bool before = (cs > sv[p]) || (cs == sv[p] && ci < si[p]);
                if (before) {
                    float tv = sv[p]; int ti = si[p];
                    sv[p] = cs; si[p] = ci; cs = tv; ci = ti;
                }
            }
        }
        // softmax-cancelled weights over exact top-4
        float e0 = 1.f;
        float e1 = expf(sv[1] - sv[0]);
        float e2 = expf(sv[2] - sv[0]);
        float e3 = expf(sv[3] - sv[0]);
        float inv = 1.f / (e0 + e1 + e2 + e3);
        topw_s[n][0] = e0*inv; topw_s[n][1] = e1*inv;
        topw_s[n][2] = e2*inv; topw_s[n][3] = e3*inv;
        topi_s[n][0] = si[0]; topi_s[n][1] = si[1];
        topi_s[n][2] = si[2]; topi_s[n][3] = si[3];
    }
    __syncthreads();

    // ---- phase 2: ctx gather, 32 (n,k) pairs, 4 per warp; lane = v index ----
    float acc = 0.f;
    #pragma unroll
    for (int pp = 0; pp < 4; pp++) {
        int p = warp * 4 + pp;
        int nn = p >> 2, k = p & 3;
        float wt = topw_s[nn][k] * sd[nn];
        int mi = topi_s[nn][k];
        const float* Kp = knowledge + (((size_t)nn * M_MEM + mi) << 10);  // * KD*VD
        float s = 0.f;
        #pragma unroll
        for (int d = 0; d < KD; d++) s += qs[d] * Kp[d * VD + lane];
        acc += wt * s;
    }
    part[warp * 32 + lane] = acc;
    __syncthreads();
    if (tid < VD) {
        float f = 0.f;
        #pragma unroll
        for (int w = 0; w < 8; w++) f += part[w * 32 + tid];
        fin[tid] = f;
    }
    __syncthreads();

    // ---- phase 3: proj + residual + LayerNorm ----
    float h[2];
    #pragma unroll
    for (int l = 0; l < 2; l++) {
        int e = tid + l * 256;
        float s = bo[e];
        #pragma unroll
        for (int v = 0; v < VD; v++) s += fin[v] * Wo[v * E_DIM + e];
        h[l] = xs[e] + s;
    }
    float sum = h[0] + h[1];
    float sq  = h[0]*h[0] + h[1]*h[1];
    #pragma unroll
    for (int o = 16; o > 0; o >>= 1) {
        sum += __shfl_down_sync(0xffffffffu, sum, o);
        sq  += __shfl_down_sync(0xffffffffu, sq,  o);
    }
    if (lane == 0) { red[warp] = sum; red[warp + 8] = sq; }
    __syncthreads();
    if (tid == 0) {
        float S = 0.f, Q = 0.f;
        #pragma unroll
        for (int w = 0; w < 8; w++) { S += red[w]; Q += red[w + 8]; }
        float mu = S * (1.f / E_DIM);
        float var = Q * (1.f / E_DIM) - mu * mu;
        s_mu = mu;
        s_inv = rsqrtf(var + 1e-5f);
    }
    __syncthreads();
    #pragma unroll
    for (int l = 0; l < 2; l++) {
        int e = tid + l * 256;
        out[(size_t)t * E_DIM + e] = (h[l] - s_mu) * s_inv * gamma[e] + beta[e];
    }
}

// ---------------------------------------------------------------------------
extern "C" void kernel_launch(void* const* d_in, const int* in_sizes, int n_in,
                              void* d_out, int out_size)
{
    // input order: x, [top_k], emb, sector_keys, memory_keys, knowledge,
    //              Wq, bq, Wo, bo, gamma, beta
    const int o = (n_in >= 12) ? 0 : -1;   // defensive: top_k scalar may be dropped
    const int*   x     = (const int*)  d_in[0];
    const float* emb   = (const float*)d_in[2 + o];
    const float* skeys = (const float*)d_in[3 + o];
    const float* mkeys = (const float*)d_in[4 + o];
    const float* knw   = (const float*)d_in[5 + o];
    const float* Wq    = (const float*)d_in[6 + o];
    const float* bq    = (const float*)d_in[7 + o];
    const float* Wo    = (const float*)d_in[8 + o];
    const float* bo    = (const float*)d_in[9 + o];
    const float* gamma = (const float*)d_in[10 + o];
    const float* beta  = (const float*)d_in[11 + o];

    float* out    = (float*)d_out;                    // [T, E] LayerNorm output
    float* out_sd = out + (size_t)T_TOK * E_DIM;      // [T, N] sector_dist

    // opt into >48KB dynamic smem for the GEMM (attribute set, not an allocation)
    cudaFuncSetAttribute(k_scores_topk,
                         cudaFuncAttributeMaxDynamicSharedMemorySize, K2_SMEM_BYTES);

    k_embed<<<T_TOK, 128>>>(x, emb, skeys, Wq, bq, out_sd);
    dim3 g2(T_TOK / BM, N_SEC);
    k_scores_topk<<<g2, 256, K2_SMEM_BYTES>>>(mkeys);
    k_tail<<<T_TOK, 256>>>(mkeys, knw, Wo, bo, gamma, beta, out);
}

// round 15
// speedup vs baseline: 1.2177x; 1.2177x over previous
#include <cuda_runtime.h>
#include <cuda_bf16.h>
#include <math.h>

// Problem constants
#define T_TOK 2048   // B*S
#define E_DIM 512
#define N_SEC 8
#define M_MEM 2048
#define KD 32
#define VD 32
#define TOPK 4
#define CAND 8       // approximate candidates kept per (token, sector)

// Scratch (device globals; no runtime allocation allowed)
__device__ float g_xemb[T_TOK * E_DIM];      // 4 MB
__device__ __nv_bfloat16 g_xemb_bf[T_TOK * E_DIM];              // 2 MB
__device__ __nv_bfloat16 g_mkeys_bf[N_SEC * M_MEM * E_DIM];     // 16.8 MB
__device__ float g_q[T_TOK * KD];
__device__ float g_sdist[T_TOK * N_SEC];
__device__ int   g_top8i[T_TOK * N_SEC * CAND];

// ---------------------------------------------------------------------------
// Kernel 0: convert mkeys fp32 -> bf16 (candidate-GEMM operand only)
// ---------------------------------------------------------------------------
__global__ void k_conv(const float* __restrict__ mkeys)
{
    size_t i = ((size_t)blockIdx.x * 256 + threadIdx.x) * 4;
    float4 v = *(const float4*)(mkeys + i);
    __nv_bfloat162 lo = __floats2bfloat162_rn(v.x, v.y);
    __nv_bfloat162 hi = __floats2bfloat162_rn(v.z, v.w);
    *(__nv_bfloat162*)(g_mkeys_bf + i)     = lo;
    *(__nv_bfloat162*)(g_mkeys_bf + i + 2) = hi;
}

// ---------------------------------------------------------------------------
// Kernel 1: embedding gather + sector softmax + token query (1 block / token)
// ---------------------------------------------------------------------------
__global__ void k_embed(const int* __restrict__ x, const float* __restrict__ emb,
                        const float* __restrict__ skeys, const float* __restrict__ Wq,
                        const float* __restrict__ bq, float* __restrict__ out_sdist)
{
    const int t = blockIdx.x;
    const int tid = threadIdx.x;          // 128 threads
    __shared__ __align__(16) float xs[E_DIM];
    __shared__ float red[128];
    __shared__ float ssc[N_SEC];

    const int xi = x[t];
    float4 v = ((const float4*)(emb + (size_t)xi * E_DIM))[tid];
    ((float4*)xs)[tid] = v;
    ((float4*)(g_xemb + (size_t)t * E_DIM))[tid] = v;
    {   // bf16 copy for the candidate GEMM
        __nv_bfloat162 lo = __floats2bfloat162_rn(v.x, v.y);
        __nv_bfloat162 hi = __floats2bfloat162_rn(v.z, v.w);
        __nv_bfloat16* dst = g_xemb_bf + (size_t)t * E_DIM + tid * 4;
        *(__nv_bfloat162*)(dst)     = lo;
        *(__nv_bfloat162*)(dst + 2) = hi;
    }

    #pragma unroll
    for (int n = 0; n < N_SEC; n++) {
        const float* sk = skeys + n * E_DIM + tid * 4;
        float p = v.x * sk[0] + v.y * sk[1] + v.z * sk[2] + v.w * sk[3];
        #pragma unroll
        for (int o = 16; o > 0; o >>= 1) p += __shfl_down_sync(0xffffffffu, p, o);
        if ((tid & 31) == 0) red[n * 4 + (tid >> 5)] = p;
    }
    __syncthreads();
    if (tid < N_SEC)
        ssc[tid] = red[tid*4] + red[tid*4+1] + red[tid*4+2] + red[tid*4+3];
    __syncthreads();
    if (tid == 0) {
        float mx = ssc[0];
        #pragma unroll
        for (int i = 1; i < N_SEC; i++) mx = fmaxf(mx, ssc[i]);
        float ex[N_SEC]; float sum = 0.f;
        #pragma unroll
        for (int i = 0; i < N_SEC; i++) { ex[i] = expf(ssc[i] - mx); sum += ex[i]; }
        float inv = 1.f / sum;
        #pragma unroll
        for (int i = 0; i < N_SEC; i++) {
            float d = ex[i] * inv;
            out_sdist[t * N_SEC + i] = d;
            g_sdist[t * N_SEC + i]   = d;
        }
    }
    // token query q = xs @ Wq + bq  (Wq is [E, KD] row-major)
    {
        const int kd = tid & 31;
        const int ch = tid >> 5;
        const int e0 = ch * 128;
        float p = 0.f;
        #pragma unroll 8
        for (int e = 0; e < 128; e++)
            p += xs[e0 + e] * Wq[(e0 + e) * KD + kd];
        __syncthreads();
        red[tid] = p;
        __syncthreads();
        if (tid < KD)
            g_q[t * KD + tid] = red[tid] + red[tid + 32] + red[tid + 64] + red[tid + 96] + bq[tid];
    }
}

// ---------------------------------------------------------------------------
// Kernel 2: bf16 tensor-core score GEMM (m16n8k16, 2x tf32 rate) + top-8.
// Grid (T_TOK/BM, N_SEC), 256 thr. Block 128x128, warps 2(M)x4(N), tile 64x32.
// 3-stage cp.async pipeline; Sc in separate smem (no aliasing).
// ---------------------------------------------------------------------------
#define BM 128
#define BN 128
#define BK 32                // bf16 elements per k-stage
#define LDBF 40              // smem row stride in bf16 (80 B = 20 words)
#define LDW  20              // same stride in 32-bit words
#define LDSC 132             // Sc row stride (floats)
#define NKT (E_DIM / BK)     // 16 k-stages
#define STG_W (BM * LDW)     // 2560 words per stage (A and B identical)
#define SC_OFF (6 * STG_W)   // Sc word offset (after 3 A + 3 B stages)
#define K2_SMEM_BYTES ((6 * STG_W + BM * LDSC) * 4)   // 129024

__device__ __forceinline__ void cp16(unsigned dst_smem, const void* src) {
    asm volatile("cp.async.cg.shared.global [%0], [%1], 16;"
                 :: "r"(dst_smem), "l"(src));
}

__global__ void __launch_bounds__(256, 1)
k_scores_topk()
{
    const int n  = blockIdx.y;
    const int t0 = blockIdx.x * BM;
    const int tid  = threadIdx.x;
    const int lane = tid & 31, warp = tid >> 5;
    const int wm = (warp & 1) * 64;       // warp M offset (warp tile 64x32)
    const int wn = (warp >> 1) * 32;      // warp N offset
    const int g  = lane >> 2, t4 = lane & 3;

    extern __shared__ __align__(16) unsigned sh[];
    unsigned* AsBase = sh;                 // 3 stages of [BM][LDW]
    unsigned* BsBase = sh + 3 * STG_W;     // 3 stages of [BN][LDW]
    float*    Sc     = (float*)(sh + SC_OFF);

    const unsigned sAs = (unsigned)__cvta_generic_to_shared(AsBase);
    const unsigned sBs = (unsigned)__cvta_generic_to_shared(BsBase);

    const __nv_bfloat16* Bg = g_mkeys_bf + (size_t)n * M_MEM * E_DIM;
    const __nv_bfloat16* Ag = g_xemb_bf + (size_t)t0 * E_DIM;

    // running approx top-8 (valid for tid < BM; token = t0 + tid)
    float rv[CAND]; int ri[CAND];
    #pragma unroll
    for (int i = 0; i < CAND; i++) { rv[i] = -1e30f; ri[i] = 0; }

    for (int m0 = 0; m0 < M_MEM; m0 += BN) {
        float acc[4][4][4];
        #pragma unroll
        for (int mi = 0; mi < 4; mi++)
            #pragma unroll
            for (int ni = 0; ni < 4; ni++)
                #pragma unroll
                for (int c = 0; c < 4; c++) acc[mi][ni][c] = 0.f;

        // ---- issue stage 0 ----  (512 x 16B per tile: 2 per thread each)
        {
            #pragma unroll
            for (int l = 0; l < 2; l++) {
                int lin = tid + l * 256;          // row = lin>>2, chunk = lin&3 (8 bf16)
                cp16(sAs + (0 * STG_W + (lin >> 2) * LDW + ((lin & 3) << 2)) * 4,
                     Ag + (size_t)(lin >> 2) * E_DIM + ((lin & 3) << 3));
            }
            #pragma unroll
            for (int l = 0; l < 2; l++) {
                int lin = tid + l * 256;
                cp16(sBs + (0 * STG_W + (lin >> 2) * LDW + ((lin & 3) << 2)) * 4,
                     Bg + (size_t)(m0 + (lin >> 2)) * E_DIM + ((lin & 3) << 3));
            }
            asm volatile("cp.async.commit_group;" ::: "memory");
        }

        for (int kt = 0; kt < NKT; kt++) {
            const int cur = kt % 3;
            if (kt < NKT - 1) {
                const int nxt = (kt + 1) % 3;
                const int k0 = (kt + 1) * BK;
                #pragma unroll
                for (int l = 0; l < 2; l++) {
                    int lin = tid + l * 256;
                    cp16(sAs + (nxt * STG_W + (lin >> 2) * LDW + ((lin & 3) << 2)) * 4,
                         Ag + (size_t)(lin >> 2) * E_DIM + k0 + ((lin & 3) << 3));
                }
                #pragma unroll
                for (int l = 0; l < 2; l++) {
                    int lin = tid + l * 256;
                    cp16(sBs + (nxt * STG_W + (lin >> 2) * LDW + ((lin & 3) << 2)) * 4,
                         Bg + (size_t)(m0 + (lin >> 2)) * E_DIM + k0 + ((lin & 3) << 3));
                }
                asm volatile("cp.async.commit_group;" ::: "memory");
                asm volatile("cp.async.wait_group 1;" ::: "memory");   // stage kt arrived
            } else {
                asm volatile("cp.async.wait_group 0;" ::: "memory");   // drain all
            }
            __syncthreads();   // stage kt visible to all; mma(kt-1) of all warps done

            const unsigned* As = AsBase + cur * STG_W;
            const unsigned* Bs = BsBase + cur * STG_W;
            // two k16 steps per 32-bf16 stage: kb2 = k/2 in words: {0, 8}
            #pragma unroll
            for (int ks = 0; ks < 2; ks++) {
                const int kb2 = ks * 8;
                unsigned a[4][4], b[4][2];
                #pragma unroll
                for (int mi = 0; mi < 4; mi++) {
                    int tr = wm + mi * 16 + g;
                    a[mi][0] = As[ tr      * LDW + kb2 + t4    ];
                    a[mi][1] = As[(tr + 8) * LDW + kb2 + t4    ];
                    a[mi][2] = As[ tr      * LDW + kb2 + t4 + 4];
                    a[mi][3] = As[(tr + 8) * LDW + kb2 + t4 + 4];
                }
                #pragma unroll
                for (int ni = 0; ni < 4; ni++) {
                    int cc = wn + ni * 8 + g;
                    b[ni][0] = Bs[cc * LDW + kb2 + t4    ];
                    b[ni][1] = Bs[cc * LDW + kb2 + t4 + 4];
                }
                #pragma unroll
                for (int mi = 0; mi < 4; mi++)
                    #pragma unroll
                    for (int ni = 0; ni < 4; ni++) {
                        asm volatile(
                            "mma.sync.aligned.m16n8k16.row.col.f32.bf16.bf16.f32 "
                            "{%0,%1,%2,%3}, {%4,%5,%6,%7}, {%8,%9}, {%0,%1,%2,%3};\n"
                            : "+f"(acc[mi][ni][0]), "+f"(acc[mi][ni][1]),
                              "+f"(acc[mi][ni][2]), "+f"(acc[mi][ni][3])
                            : "r"(a[mi][0]), "r"(a[mi][1]), "r"(a[mi][2]), "r"(a[mi][3]),
                              "r"(b[ni][0]), "r"(b[ni][1]));
                    }
            }
        }
        __syncthreads();   // all warps done with mma reads of this m-tile

        // write score tile from C fragments (Sc separate; no aliasing)
        #pragma unroll
        for (int mi = 0; mi < 4; mi++) {
            #pragma unroll
            for (int ni = 0; ni < 4; ni++) {
                int row = wm + mi * 16 + g;
                int col = wn + ni * 8 + 2 * t4;
                *(float2*)(Sc + row * LDSC + col) =
                    make_float2(acc[mi][ni][0], acc[mi][ni][1]);
                *(float2*)(Sc + (row + 8) * LDSC + col) =
                    make_float2(acc[mi][ni][2], acc[mi][ni][3]);
            }
        }
        __syncthreads();
        if (tid < BM) {
            const float4* rowp = (const float4*)(Sc + tid * LDSC);
            #pragma unroll 4
            for (int q = 0; q < BN / 4; q++) {
                float4 s4 = rowp[q];
                const float sv[4] = {s4.x, s4.y, s4.z, s4.w};
                #pragma unroll
                for (int e = 0; e < 4; e++) {
                    float s = sv[e];
                    if (s > rv[CAND-1]) {
                        float cs = s; int ci = m0 + q * 4 + e;
                        #pragma unroll
                        for (int p = 0; p < CAND; p++) {
                            if (cs > rv[p]) {
                                float tv = rv[p]; int ti = ri[p];
                                rv[p] = cs; ri[p] = ci; cs = tv; ci = ti;
                            }
                        }
                    }
                }
            }
        }
        __syncthreads();   // scan done before next m-tile's cp.async overwrites stage 0
    }

    if (tid < BM) {
        size_t base = ((size_t)(t0 + tid) * N_SEC + n) * CAND;
        #pragma unroll
        for (int j = 0; j < CAND; j++) g_top8i[base + j] = ri[j];
    }
}

// ---------------------------------------------------------------------------
// Kernel 3 (fused tail): exact fp32 rescore of the 8 candidates -> top-4
// weights (in smem), then ctx gather + sector mix + proj + residual + LN.
// 1 block / token, 256 threads; rescore warp n = sector n.
// ---------------------------------------------------------------------------
__global__ void k_tail(const float* __restrict__ mkeys,
                       const float* __restrict__ knowledge,
                       const float* __restrict__ Wo, const float* __restrict__ bo,
                       const float* __restrict__ gamma, const float* __restrict__ beta,
                       float* __restrict__ out)
{
    const int t = blockIdx.x;
    const int tid = threadIdx.x;          // 256 threads
    const int lane = tid & 31, warp = tid >> 5;
    __shared__ __align__(16) float xs[E_DIM];
    __shared__ float sc8[N_SEC][CAND];
    __shared__ float topw_s[N_SEC][TOPK];
    __shared__ int   topi_s[N_SEC][TOPK];
    __shared__ float qs[KD], sd[N_SEC], fin[VD];
    __shared__ float part[8 * 32];
    __shared__ float red[16];
    __shared__ float s_mu, s_inv;

    if (tid < 128)
        ((float4*)xs)[tid] = ((const float4*)(g_xemb + (size_t)t * E_DIM))[tid];
    if (tid < KD)    qs[tid] = g_q[t * KD + tid];
    if (tid < N_SEC) sd[tid] = g_sdist[t * N_SEC + tid];
    __syncthreads();

    // ---- phase 1: exact rescore (warp = sector) ----
    const int n = warp;
    const size_t cbase = ((size_t)t * N_SEC + n) * CAND;
    const float4* xp = (const float4*)(xs + lane * 16);
    #pragma unroll
    for (int j = 0; j < CAND; j++) {
        const int mi = g_top8i[cbase + j];
        const float4* mk = (const float4*)(mkeys + ((size_t)n * M_MEM + mi) * E_DIM + lane * 16);
        float p = 0.f;
        #pragma unroll
        for (int q = 0; q < 4; q++) {
            float4 a = xp[q], b = mk[q];
            p += a.x*b.x + a.y*b.y + a.z*b.z + a.w*b.w;
        }
        #pragma unroll
        for (int o = 16; o > 0; o >>= 1) p += __shfl_down_sync(0xffffffffu, p, o);
        if (lane == 0) sc8[n][j] = p;
    }
    if (lane == 0) {
        float sv[CAND]; int si[CAND];
        #pragma unroll
        for (int i = 0; i < CAND; i++) { sv[i] = -1e30f; si[i] = 0x7fffffff; }
        #pragma unroll
        for (int j = 0; j < CAND; j++) {
            float cs = sc8[n][j]; int ci = g_top8i[cbase + j];
            #pragma unroll
            for (int p = 0; p < CAND; p++) {
                bool before = (cs > sv[p]) || (cs == sv[p] && ci < si[p]);
                if (before) {
                    float tv = sv[p]; int ti = si[p];
                    sv[p] = cs; si[p] = ci; cs = tv; ci = ti;
                }
            }
        }
        // softmax-cancelled weights over exact top-4
        float e0 = 1.f;
        float e1 = expf(sv[1] - sv[0]);
        float e2 = expf(sv[2] - sv[0]);
        float e3 = expf(sv[3] - sv[0]);
        float inv = 1.f / (e0 + e1 + e2 + e3);
        topw_s[n][0] = e0*inv; topw_s[n][1] = e1*inv;
        topw_s[n][2] = e2*inv; topw_s[n][3] = e3*inv;
        topi_s[n][0] = si[0]; topi_s[n][1] = si[1];
        topi_s[n][2] = si[2]; topi_s[n][3] = si[3];
    }
    __syncthreads();

    // ---- phase 2: ctx gather, 32 (n,k) pairs, 4 per warp; lane = v index ----
    float acc = 0.f;
    #pragma unroll
    for (int pp = 0; pp < 4; pp++) {
        int p = warp * 4 + pp;
        int nn = p >> 2, k = p & 3;
        float wt = topw_s[nn][k] * sd[nn];
        int mi = topi_s[nn][k];
        const float* Kp = knowledge + (((size_t)nn * M_MEM + mi) << 10);  // * KD*VD
        float s = 0.f;
        #pragma unroll
        for (int d = 0; d < KD; d++) s += qs[d] * Kp[d * VD + lane];
        acc += wt * s;
    }
    part[warp * 32 + lane] = acc;
    __syncthreads();
    if (tid < VD) {
        float f = 0.f;
        #pragma unroll
        for (int w = 0; w < 8; w++) f += part[w * 32 + tid];
        fin[tid] = f;
    }
    __syncthreads();

    // ---- phase 3: proj + residual + LayerNorm ----
    float h[2];
    #pragma unroll
    for (int l = 0; l < 2; l++) {
        int e = tid + l * 256;
        float s = bo[e];
        #pragma unroll
        for (int v = 0; v < VD; v++) s += fin[v] * Wo[v * E_DIM + e];
        h[l] = xs[e] + s;
    }
    float sum = h[0] + h[1];
    float sq  = h[0]*h[0] + h[1]*h[1];
    #pragma unroll
    for (int o = 16; o > 0; o >>= 1) {
        sum += __shfl_down_sync(0xffffffffu, sum, o);
        sq  += __shfl_down_sync(0xffffffffu, sq,  o);
    }
    if (lane == 0) { red[warp] = sum; red[warp + 8] = sq; }
    __syncthreads();
    if (tid == 0) {
        float S = 0.f, Q = 0.f;
        #pragma unroll
        for (int w = 0; w < 8; w++) { S += red[w]; Q += red[w + 8]; }
        float mu = S * (1.f / E_DIM);
        float var = Q * (1.f / E_DIM) - mu * mu;
        s_mu = mu;
        s_inv = rsqrtf(var + 1e-5f);
    }
    __syncthreads();
    #pragma unroll
    for (int l = 0; l < 2; l++) {
        int e = tid + l * 256;
        out[(size_t)t * E_DIM + e] = (h[l] - s_mu) * s_inv * gamma[e] + beta[e];
    }
}

// ---------------------------------------------------------------------------
extern "C" void kernel_launch(void* const* d_in, const int* in_sizes, int n_in,
                              void* d_out, int out_size)
{
    // input order: x, [top_k], emb, sector_keys, memory_keys, knowledge,
    //              Wq, bq, Wo, bo, gamma, beta
    const int o = (n_in >= 12) ? 0 : -1;   // defensive: top_k scalar may be dropped
    const int*   x     = (const int*)  d_in[0];
    const float* emb   = (const float*)d_in[2 + o];
    const float* skeys = (const float*)d_in[3 + o];
    const float* mkeys = (const float*)d_in[4 + o];
    const float* knw   = (const float*)d_in[5 + o];
    const float* Wq    = (const float*)d_in[6 + o];
    const float* bq    = (const float*)d_in[7 + o];
    const float* Wo    = (const float*)d_in[8 + o];
    const float* bo    = (const float*)d_in[9 + o];
    const float* gamma = (const float*)d_in[10 + o];
    const float* beta  = (const float*)d_in[11 + o];

    float* out    = (float*)d_out;                    // [T, E] LayerNorm output
    float* out_sd = out + (size_t)T_TOK * E_DIM;      // [T, N] sector_dist

    // opt into >48KB dynamic smem for the GEMM (attribute set, not an allocation)
    cudaFuncSetAttribute(k_scores_topk,
                         cudaFuncAttributeMaxDynamicSharedMemorySize, K2_SMEM_BYTES);

    k_conv<<<(N_SEC * M_MEM * E_DIM) / 1024, 256>>>(mkeys);
    k_embed<<<T_TOK, 128>>>(x, emb, skeys, Wq, bq, out_sd);
    dim3 g2(T_TOK / BM, N_SEC);
    k_scores_topk<<<g2, 256, K2_SMEM_BYTES>>>();
    k_tail<<<T_TOK, 256>>>(mkeys, knw, Wo, bo, gamma, beta, out);
}